// round 15
// baseline (speedup 1.0000x reference)
#include <cuda_runtime.h>
#include <cuda_fp16.h>
#include <cstdint>

#define NN 100000
#define EE 3200000
#define DD 128
#define BN_EPS 1e-5f
#define CAP 64                         // slots per node (deg ~ Poisson(32))
#define MAXOVF (1 << 18)               // overflow capacity (pairs)

#define EDGE_BLOCKS (EE / 4 / 256)            // 3125
#define H16_BLOCKS  (NN * DD / 8 / 256 + 1)   // 6251
#define WT_BLOCKS   (128 * 256 / 256)         // 128
#define FUSED_BLOCKS (EDGE_BLOCKS + H16_BLOCKS + WT_BLOCKS)

// ---- scratch (device globals) ----
__device__ int    g_count[NN];
__device__ int    g_slots[(size_t)NN * CAP];   // src indices, slot r = rank r
__device__ int    g_ovf[2 * MAXOVF];           // (dst, src) pairs for rank >= CAP
__device__ int    g_ovf_ctr;
__device__ __half g_h16[(size_t)NN * DD];
__device__ __half g_neigh16[(size_t)NN * DD];
__device__ __half g_rst16[(size_t)NN * DD];
__device__ __half g_Wt16[128 * 256];           // [n][k] fp16 W^T over [W_self; W_neigh]
__device__ float  g_colsum[DD];
__device__ float  g_colsumsq[DD];

// ================= helpers =================
__device__ __forceinline__ uint32_t smem_u32(const void* p) {
    uint32_t a;
    asm("{ .reg .u64 t; cvta.to.shared.u64 t, %1; cvt.u32.u64 %0, t; }" : "=r"(a) : "l"(p));
    return a;
}
__device__ __forceinline__ void cp16(uint32_t saddr, const void* gaddr, bool valid) {
    asm volatile("cp.async.cg.shared.global [%0], [%1], 16, %2;"
                 :: "r"(saddr), "l"(gaddr), "r"(valid ? 16u : 0u) : "memory");
}
#define CP_COMMIT() asm volatile("cp.async.commit_group;" ::: "memory")
#define CP_WAIT(N)  asm volatile("cp.async.wait_group %0;" :: "n"(N) : "memory")

__device__ __forceinline__ void mma16(float* d, uint32_t a0, uint32_t a1, uint32_t a2,
                                      uint32_t a3, uint32_t b0, uint32_t b1) {
    asm volatile(
        "mma.sync.aligned.m16n8k16.row.col.f32.f16.f16.f32 "
        "{%0,%1,%2,%3}, {%4,%5,%6,%7}, {%8,%9}, {%0,%1,%2,%3};"
        : "+f"(d[0]), "+f"(d[1]), "+f"(d[2]), "+f"(d[3])
        : "r"(a0), "r"(a1), "r"(a2), "r"(a3), "r"(b0), "r"(b1));
}
__device__ __forceinline__ void ldsm_x4(uint32_t& r0, uint32_t& r1, uint32_t& r2,
                                        uint32_t& r3, uint32_t addr) {
    asm volatile("ldmatrix.sync.aligned.m8n8.x4.shared.b16 {%0,%1,%2,%3}, [%4];"
                 : "=r"(r0), "=r"(r1), "=r"(r2), "=r"(r3) : "r"(addr));
}

// ---------------------------------------------------------------- zero
__global__ void k_zero() {
    int i = blockIdx.x * blockDim.x + threadIdx.x;
    if (i < NN) g_count[i] = 0;
    if (i < DD) { g_colsum[i] = 0.f; g_colsumsq[i] = 0.f; }
    if (i == 0) g_ovf_ctr = 0;
}

// ---------------------------------------------------------------- fused: edge-slot build | h->fp16 | W^T fp16
__device__ __forceinline__ void place_edge(int d, int s) {
    int r = atomicAdd(&g_count[d], 1);
    if (r < CAP) {
        g_slots[(size_t)d * CAP + r] = s;
    } else {
        int idx = atomicAdd(&g_ovf_ctr, 1);
        if (idx < MAXOVF) { g_ovf[2 * idx] = d; g_ovf[2 * idx + 1] = s; }
    }
}
__global__ void k_build(const int* __restrict__ dst,
                        const int* __restrict__ src,
                        const float* __restrict__ h,
                        const float* __restrict__ Ws,
                        const float* __restrict__ Wn) {
    int b = blockIdx.x;
    if (b < EDGE_BLOCKS) {
        int e4 = b * 256 + threadIdx.x;
        if (e4 >= EE / 4) return;
        int4 d = ((const int4*)dst)[e4];
        int4 s = ((const int4*)src)[e4];
        place_edge(d.x, s.x);
        place_edge(d.y, s.y);
        place_edge(d.z, s.z);
        place_edge(d.w, s.w);
    } else if (b < EDGE_BLOCKS + H16_BLOCKS) {
        int i = (b - EDGE_BLOCKS) * 256 + threadIdx.x;
        const int TOT = NN * DD / 8;
        if (i >= TOT) return;
        float4 a = ((const float4*)h)[2 * i];
        float4 bb = ((const float4*)h)[2 * i + 1];
        __half2 r[4];
        r[0] = __float22half2_rn(make_float2(a.x, a.y));
        r[1] = __float22half2_rn(make_float2(a.z, a.w));
        r[2] = __float22half2_rn(make_float2(bb.x, bb.y));
        r[3] = __float22half2_rn(make_float2(bb.z, bb.w));
        ((uint4*)g_h16)[i] = *(uint4*)r;
    } else {
        int i = (b - EDGE_BLOCKS - H16_BLOCKS) * 256 + threadIdx.x;
        if (i >= 128 * 256) return;
        int n = i >> 8, k = i & 255;
        float v = (k < 128) ? Ws[(size_t)k * DD + n] : Wn[(size_t)(k - 128) * DD + n];
        g_Wt16[i] = __float2half_rn(v);
    }
}

// ---------------------------------------------------------------- segment mean (1 warp / node, fp16 gather)
__global__ void k_aggregate() {
    int gwarp = (blockIdx.x * blockDim.x + threadIdx.x) >> 5;
    if (gwarp >= NN) return;
    int lane = threadIdx.x & 31;
    int start = gwarp * CAP;
    int deg = g_count[gwarp];
    int main_n = (deg < CAP) ? deg : CAP;

    float accA[4] = {0, 0, 0, 0};
    float accB[4] = {0, 0, 0, 0};

    int i = 0;
    for (; i + 32 <= main_n; i += 32) {
        int s = g_slots[start + i + lane];
#pragma unroll
        for (int j = 0; j < 32; j += 2) {
            int s0 = __shfl_sync(0xffffffffu, s, j);
            int s1 = __shfl_sync(0xffffffffu, s, j + 1);
            uint2 u0 = *((const uint2*)(g_h16 + (size_t)s0 * DD) + lane);
            uint2 u1 = *((const uint2*)(g_h16 + (size_t)s1 * DD) + lane);
            {
                float2 f0 = __half22float2(*(__half2*)&u0.x);
                float2 f1 = __half22float2(*(__half2*)&u0.y);
                accA[0] += f0.x; accA[1] += f0.y; accA[2] += f1.x; accA[3] += f1.y;
            }
            {
                float2 f0 = __half22float2(*(__half2*)&u1.x);
                float2 f1 = __half22float2(*(__half2*)&u1.y);
                accB[0] += f0.x; accB[1] += f0.y; accB[2] += f1.x; accB[3] += f1.y;
            }
        }
    }
    {
        int rem = main_n - i;
        int s = (lane < rem) ? g_slots[start + i + lane] : 0;
        for (int j = 0; j < rem; j++) {
            int sj = __shfl_sync(0xffffffffu, s, j);
            uint2 u = *((const uint2*)(g_h16 + (size_t)sj * DD) + lane);
            float2 f0 = __half22float2(*(__half2*)&u.x);
            float2 f1 = __half22float2(*(__half2*)&u.y);
            accA[0] += f0.x; accA[1] += f0.y; accA[2] += f1.x; accA[3] += f1.y;
        }
    }
    if (deg > CAP) {
        int n = g_ovf_ctr;
        if (n > MAXOVF) n = MAXOVF;
        for (int o = 0; o < n; o++) {
            if (g_ovf[2 * o] == gwarp) {
                int sj = g_ovf[2 * o + 1];
                uint2 u = *((const uint2*)(g_h16 + (size_t)sj * DD) + lane);
                float2 f0 = __half22float2(*(__half2*)&u.x);
                float2 f1 = __half22float2(*(__half2*)&u.y);
                accA[0] += f0.x; accA[1] += f0.y; accA[2] += f1.x; accA[3] += f1.y;
            }
        }
    }
    float inv = 1.0f / fmaxf((float)deg, 1.0f);
    __half2 p0 = __float22half2_rn(make_float2((accA[0] + accB[0]) * inv,
                                               (accA[1] + accB[1]) * inv));
    __half2 p1 = __float22half2_rn(make_float2((accA[2] + accB[2]) * inv,
                                               (accA[3] + accB[3]) * inv));
    uint2 o;
    o.x = *(uint32_t*)&p0;
    o.y = *(uint32_t*)&p1;
    *((uint2*)(g_neigh16 + (size_t)gwarp * DD) + lane) = o;
}

// ---------------------------------------------------------------- FP16 mma.sync GEMM
// Block tile 128(M) x 64(N), 8 warps (4M x 2N), warp tile 32x32.
// 4-stage cp.async pipeline, ldmatrix fragments, 3 CTAs/SM.
#define STRD16 40
#define A_CH (128 * STRD16)            // halves per A stage
#define B_CH (64 * STRD16)             // halves per B stage
__global__ __launch_bounds__(256, 3) void k_gemm(const float* __restrict__ bias) {
    extern __shared__ __half sm16[];
    __half* As = sm16;
    __half* Bs = sm16 + 4 * A_CH;
    float* cs = (float*)(sm16 + 4 * A_CH + 4 * B_CH);
    float* cq = cs + 64;

    int tid = threadIdx.x;
    int wid = tid >> 5, lane = tid & 31;
    int g = lane >> 2, t = lane & 3;
    int warpM = wid >> 1, warpN = wid & 1;
    int bx = blockIdx.x;
    int m0 = (bx >> 1) * 128;
    int n0 = (bx & 1) * 64;

    if (tid < 64) { cs[tid] = 0.f; cq[tid] = 0.f; }

    uint32_t sbA = smem_u32(As), sbB = smem_u32(Bs);

    int lane7 = lane & 7;
    int aRow = ((lane >> 3) & 1) * 8 + lane7;
    int aK   = ((lane >> 4) & 1) * 8;
    int bRow = ((lane >> 4) & 1) * 8 + lane7;
    int bK   = ((lane >> 3) & 1) * 8;

    auto issue = [&](int kk, int st) {
        uint32_t ab = sbA + (uint32_t)(st * A_CH) * 2u;
#pragma unroll
        for (int i = 0; i < 2; i++) {
            int slot = tid + i * 256;           // 512 slots: 128 rows x 4 segs
            int row = slot >> 2, seg = slot & 3;
            int gm = m0 + row;
            const __half* gp = (kk < 4)
                ? (g_h16 + (size_t)gm * DD + kk * 32 + seg * 8)
                : (g_neigh16 + (size_t)gm * DD + (kk - 4) * 32 + seg * 8);
            cp16(ab + row * (STRD16 * 2) + seg * 16, gp, gm < NN);
        }
        uint32_t bb = sbB + (uint32_t)(st * B_CH) * 2u;
        {
            int row = tid >> 2, seg = tid & 3;  // 256 slots: 64 rows x 4 segs
            cp16(bb + row * (STRD16 * 2) + seg * 16,
                 g_Wt16 + (size_t)(n0 + row) * 256 + kk * 32 + seg * 8, true);
        }
        CP_COMMIT();
    };

    float acc[2][4][4];
#pragma unroll
    for (int a = 0; a < 2; a++)
#pragma unroll
        for (int b = 0; b < 4; b++)
#pragma unroll
            for (int c = 0; c < 4; c++) acc[a][b][c] = 0.f;

    issue(0, 0);
    issue(1, 1);

#pragma unroll
    for (int kk = 0; kk < 8; kk++) {
        if (kk < 6) issue(kk + 2, (kk + 2) & 3);
        if (kk < 6)      { CP_WAIT(2); }
        else if (kk == 6){ CP_WAIT(1); }
        else             { CP_WAIT(0); }
        __syncthreads();

        int st = kk & 3;
        uint32_t ab = sbA + (uint32_t)(st * A_CH) * 2u;
        uint32_t bb = sbB + (uint32_t)(st * B_CH) * 2u;
#pragma unroll
        for (int ks = 0; ks < 2; ks++) {
            int kb = ks * 16;
            uint32_t bf[4][2];
#pragma unroll
            for (int pair = 0; pair < 2; pair++) {
                int nb = warpN * 32 + pair * 16;
                uint32_t addr = bb + (uint32_t)((nb + bRow) * STRD16 + kb + bK) * 2u;
                ldsm_x4(bf[2 * pair][0], bf[2 * pair][1],
                        bf[2 * pair + 1][0], bf[2 * pair + 1][1], addr);
            }
#pragma unroll
            for (int mf = 0; mf < 2; mf++) {
                int m = warpM * 32 + mf * 16;
                uint32_t a0, a1, a2, a3;
                uint32_t addr = ab + (uint32_t)((m + aRow) * STRD16 + kb + aK) * 2u;
                ldsm_x4(a0, a1, a2, a3, addr);
#pragma unroll
                for (int nf = 0; nf < 4; nf++)
                    mma16(acc[mf][nf], a0, a1, a2, a3, bf[nf][0], bf[nf][1]);
            }
        }
    }

    // ---- epilogue: bias + relu, fp16 store, per-block BN partials (fp32 exact) ----
#pragma unroll
    for (int nf = 0; nf < 4; nf++) {
        int col = warpN * 32 + nf * 8 + 2 * t;      // 0..63 local
        int gcol = n0 + col;
        float2 bv = *(const float2*)(bias + gcol);
        float s0 = 0.f, s1 = 0.f, q0 = 0.f, q1 = 0.f;
#pragma unroll
        for (int mf = 0; mf < 2; mf++) {
#pragma unroll
            for (int hh = 0; hh < 2; hh++) {
                int row = m0 + warpM * 32 + mf * 16 + g + hh * 8;
                float v0 = fmaxf(acc[mf][nf][hh * 2 + 0] + bv.x, 0.f);
                float v1 = fmaxf(acc[mf][nf][hh * 2 + 1] + bv.y, 0.f);
                if (row < NN) {
                    __half2 p = __float22half2_rn(make_float2(v0, v1));
                    *(__half2*)(g_rst16 + (size_t)row * DD + gcol) = p;
                    s0 += v0; q0 += v0 * v0;
                    s1 += v1; q1 += v1 * v1;
                }
            }
        }
        atomicAdd(&cs[col], s0);     atomicAdd(&cs[col + 1], s1);
        atomicAdd(&cq[col], q0);     atomicAdd(&cq[col + 1], q1);
    }
    __syncthreads();
    if (tid < 64) {
        atomicAdd(&g_colsum[n0 + tid], cs[tid]);
        atomicAdd(&g_colsumsq[n0 + tid], cq[tid]);
    }
}

// ---------------------------------------------------------------- normalize + residual (BN fold inline)
__global__ __launch_bounds__(256) void k_final(const float* __restrict__ h,
                                               const float* __restrict__ gamma,
                                               const float* __restrict__ beta,
                                               float* __restrict__ out) {
    __shared__ float s_scale[DD];
    __shared__ float s_shift[DD];
    if (threadIdx.x < DD) {
        int j = threadIdx.x;
        float mean = g_colsum[j] / (float)NN;
        float var = g_colsumsq[j] / (float)NN - mean * mean;
        float rs = rsqrtf(var + BN_EPS);
        float sc = rs * gamma[j];
        s_scale[j] = sc;
        s_shift[j] = beta[j] - mean * sc;
    }
    __syncthreads();

    int i4 = blockIdx.x * blockDim.x + threadIdx.x;
    const int TOT = NN * DD / 4;
    if (i4 >= TOT) return;
    int c4 = i4 & 31;
    uint2 u = ((const uint2*)g_rst16)[i4];
    float2 r0 = __half22float2(*(__half2*)&u.x);
    float2 r1 = __half22float2(*(__half2*)&u.y);
    float4 hv = ((const float4*)h)[i4];
    float4 sc = *((const float4*)s_scale + c4);
    float4 sh = *((const float4*)s_shift + c4);
    float4 o;
    o.x = hv.x + r0.x * sc.x + sh.x;
    o.y = hv.y + r0.y * sc.y + sh.y;
    o.z = hv.z + r1.x * sc.z + sh.z;
    o.w = hv.w + r1.y * sc.w + sh.w;
    ((float4*)out)[i4] = o;
}

// ---------------------------------------------------------------- launch
extern "C" void kernel_launch(void* const* d_in, const int* in_sizes, int n_in,
                              void* d_out, int out_size) {
    const float* h     = (const float*)d_in[0];
    const int*   src   = (const int*)d_in[1];
    const int*   dst   = (const int*)d_in[2];
    const float* Ws    = (const float*)d_in[3];
    const float* Wn    = (const float*)d_in[4];
    const float* bias  = (const float*)d_in[5];
    const float* gamma = (const float*)d_in[6];
    const float* beta  = (const float*)d_in[7];
    float* out = (float*)d_out;

    const int GEMM_SMEM = (4 * A_CH + 4 * B_CH) * 2 + 128 * 4;   // 61952
    static bool attr_set = false;
    if (!attr_set) {
        cudaFuncSetAttribute(k_gemm, cudaFuncAttributeMaxDynamicSharedMemorySize, GEMM_SMEM);
        attr_set = true;
    }

    k_zero<<<(NN + 255) / 256, 256>>>();
    k_build<<<FUSED_BLOCKS, 256>>>(dst, src, h, Ws, Wn);
    k_aggregate<<<(NN * 32 + 255) / 256, 256>>>();
    k_gemm<<<((NN + 127) / 128) * 2, 256, GEMM_SMEM>>>(bias);
    k_final<<<(NN * DD / 4 + 255) / 256, 256>>>(h, gamma, beta, out);
}

// round 16
// speedup vs baseline: 1.0677x; 1.0677x over previous
#include <cuda_runtime.h>
#include <cuda_fp16.h>
#include <cstdint>

#define NN 100000
#define EE 3200000
#define DD 128
#define BN_EPS 1e-5f
#define CAP 64                         // slots per node (deg ~ Poisson(32))
#define MAXOVF (1 << 18)               // overflow capacity (pairs)

#define EDGE_BLOCKS (EE / 4 / 256)            // 3125
#define H16_BLOCKS  (NN * DD / 8 / 256 + 1)   // 6251
#define WT_BLOCKS   (128 * 256 / 256)         // 128
#define FUSED_BLOCKS (EDGE_BLOCKS + H16_BLOCKS + WT_BLOCKS)

// ---- scratch (device globals) ----
__device__ int    g_count[NN];
__device__ int    g_slots[(size_t)NN * CAP];   // src indices, slot r = rank r
__device__ int    g_ovf[2 * MAXOVF];           // (dst, src) pairs for rank >= CAP
__device__ int    g_ovf_ctr;
__device__ __half g_h16[(size_t)NN * DD];
__device__ __half g_neigh16[(size_t)NN * DD];
__device__ __half g_rst16[(size_t)NN * DD];
__device__ __half g_Wt16[128 * 256];           // [n][k] fp16 W^T over [W_self; W_neigh]
__device__ float  g_colsum[DD];
__device__ float  g_colsumsq[DD];

// ================= helpers =================
__device__ __forceinline__ uint32_t smem_u32(const void* p) {
    uint32_t a;
    asm("{ .reg .u64 t; cvta.to.shared.u64 t, %1; cvt.u32.u64 %0, t; }" : "=r"(a) : "l"(p));
    return a;
}
__device__ __forceinline__ void cp16(uint32_t saddr, const void* gaddr, bool valid) {
    asm volatile("cp.async.cg.shared.global [%0], [%1], 16, %2;"
                 :: "r"(saddr), "l"(gaddr), "r"(valid ? 16u : 0u) : "memory");
}
#define CP_COMMIT() asm volatile("cp.async.commit_group;" ::: "memory")
#define CP_WAIT(N)  asm volatile("cp.async.wait_group %0;" :: "n"(N) : "memory")

__device__ __forceinline__ void mma16(float* d, uint32_t a0, uint32_t a1, uint32_t a2,
                                      uint32_t a3, uint32_t b0, uint32_t b1) {
    asm volatile(
        "mma.sync.aligned.m16n8k16.row.col.f32.f16.f16.f32 "
        "{%0,%1,%2,%3}, {%4,%5,%6,%7}, {%8,%9}, {%0,%1,%2,%3};"
        : "+f"(d[0]), "+f"(d[1]), "+f"(d[2]), "+f"(d[3])
        : "r"(a0), "r"(a1), "r"(a2), "r"(a3), "r"(b0), "r"(b1));
}
__device__ __forceinline__ void ldsm_x4(uint32_t& r0, uint32_t& r1, uint32_t& r2,
                                        uint32_t& r3, uint32_t addr) {
    asm volatile("ldmatrix.sync.aligned.m8n8.x4.shared.b16 {%0,%1,%2,%3}, [%4];"
                 : "=r"(r0), "=r"(r1), "=r"(r2), "=r"(r3) : "r"(addr));
}

// ---------------------------------------------------------------- zero
__global__ void k_zero() {
    int i = blockIdx.x * blockDim.x + threadIdx.x;
    if (i < NN) g_count[i] = 0;
    if (i < DD) { g_colsum[i] = 0.f; g_colsumsq[i] = 0.f; }
    if (i == 0) g_ovf_ctr = 0;
}

// ---------------------------------------------------------------- fused: edge-slot build | h->fp16 | W^T fp16
__device__ __forceinline__ void place_edge(int d, int s) {
    int r = atomicAdd(&g_count[d], 1);
    if (r < CAP) {
        g_slots[(size_t)d * CAP + r] = s;
    } else {
        int idx = atomicAdd(&g_ovf_ctr, 1);
        if (idx < MAXOVF) { g_ovf[2 * idx] = d; g_ovf[2 * idx + 1] = s; }
    }
}
__global__ void k_build(const int* __restrict__ dst,
                        const int* __restrict__ src,
                        const float* __restrict__ h,
                        const float* __restrict__ Ws,
                        const float* __restrict__ Wn) {
    int b = blockIdx.x;
    if (b < EDGE_BLOCKS) {
        int e4 = b * 256 + threadIdx.x;
        if (e4 >= EE / 4) return;
        int4 d = ((const int4*)dst)[e4];
        int4 s = ((const int4*)src)[e4];
        place_edge(d.x, s.x);
        place_edge(d.y, s.y);
        place_edge(d.z, s.z);
        place_edge(d.w, s.w);
    } else if (b < EDGE_BLOCKS + H16_BLOCKS) {
        int i = (b - EDGE_BLOCKS) * 256 + threadIdx.x;
        const int TOT = NN * DD / 8;
        if (i >= TOT) return;
        float4 a = ((const float4*)h)[2 * i];
        float4 bb = ((const float4*)h)[2 * i + 1];
        __half2 r[4];
        r[0] = __float22half2_rn(make_float2(a.x, a.y));
        r[1] = __float22half2_rn(make_float2(a.z, a.w));
        r[2] = __float22half2_rn(make_float2(bb.x, bb.y));
        r[3] = __float22half2_rn(make_float2(bb.z, bb.w));
        ((uint4*)g_h16)[i] = *(uint4*)r;
    } else {
        int i = (b - EDGE_BLOCKS - H16_BLOCKS) * 256 + threadIdx.x;
        if (i >= 128 * 256) return;
        int n = i >> 8, k = i & 255;
        float v = (k < 128) ? Ws[(size_t)k * DD + n] : Wn[(size_t)(k - 128) * DD + n];
        g_Wt16[i] = __float2half_rn(v);
    }
}

// ---------------------------------------------------------------- segment mean (1 warp / node, fp16 gather)
__global__ void k_aggregate() {
    int gwarp = (blockIdx.x * blockDim.x + threadIdx.x) >> 5;
    if (gwarp >= NN) return;
    int lane = threadIdx.x & 31;
    int start = gwarp * CAP;
    int deg = g_count[gwarp];
    int main_n = (deg < CAP) ? deg : CAP;

    float accA[4] = {0, 0, 0, 0};
    float accB[4] = {0, 0, 0, 0};

    int i = 0;
    for (; i + 32 <= main_n; i += 32) {
        int s = g_slots[start + i + lane];
#pragma unroll
        for (int j = 0; j < 32; j += 2) {
            int s0 = __shfl_sync(0xffffffffu, s, j);
            int s1 = __shfl_sync(0xffffffffu, s, j + 1);
            uint2 u0 = *((const uint2*)(g_h16 + (size_t)s0 * DD) + lane);
            uint2 u1 = *((const uint2*)(g_h16 + (size_t)s1 * DD) + lane);
            {
                float2 f0 = __half22float2(*(__half2*)&u0.x);
                float2 f1 = __half22float2(*(__half2*)&u0.y);
                accA[0] += f0.x; accA[1] += f0.y; accA[2] += f1.x; accA[3] += f1.y;
            }
            {
                float2 f0 = __half22float2(*(__half2*)&u1.x);
                float2 f1 = __half22float2(*(__half2*)&u1.y);
                accB[0] += f0.x; accB[1] += f0.y; accB[2] += f1.x; accB[3] += f1.y;
            }
        }
    }
    {
        int rem = main_n - i;
        int s = (lane < rem) ? g_slots[start + i + lane] : 0;
        for (int j = 0; j < rem; j++) {
            int sj = __shfl_sync(0xffffffffu, s, j);
            uint2 u = *((const uint2*)(g_h16 + (size_t)sj * DD) + lane);
            float2 f0 = __half22float2(*(__half2*)&u.x);
            float2 f1 = __half22float2(*(__half2*)&u.y);
            accA[0] += f0.x; accA[1] += f0.y; accA[2] += f1.x; accA[3] += f1.y;
        }
    }
    if (deg > CAP) {
        int n = g_ovf_ctr;
        if (n > MAXOVF) n = MAXOVF;
        for (int o = 0; o < n; o++) {
            if (g_ovf[2 * o] == gwarp) {
                int sj = g_ovf[2 * o + 1];
                uint2 u = *((const uint2*)(g_h16 + (size_t)sj * DD) + lane);
                float2 f0 = __half22float2(*(__half2*)&u.x);
                float2 f1 = __half22float2(*(__half2*)&u.y);
                accA[0] += f0.x; accA[1] += f0.y; accA[2] += f1.x; accA[3] += f1.y;
            }
        }
    }
    float inv = 1.0f / fmaxf((float)deg, 1.0f);
    __half2 p0 = __float22half2_rn(make_float2((accA[0] + accB[0]) * inv,
                                               (accA[1] + accB[1]) * inv));
    __half2 p1 = __float22half2_rn(make_float2((accA[2] + accB[2]) * inv,
                                               (accA[3] + accB[3]) * inv));
    uint2 o;
    o.x = *(uint32_t*)&p0;
    o.y = *(uint32_t*)&p1;
    *((uint2*)(g_neigh16 + (size_t)gwarp * DD) + lane) = o;
}

// ---------------------------------------------------------------- FP16 mma.sync GEMM
// Block tile 128x128, 8 warps (2M x 4N), ldmatrix fragments,
// 4-stage cp.async ring with wait_group 2 (two stages in flight).
#define STRD16 40
#define CH16 (128 * STRD16)            // halves per (A or B) stage
__global__ __launch_bounds__(256, 2) void k_gemm(const float* __restrict__ bias) {
    extern __shared__ __half sm16[];
    __half* As = sm16;                         // 4 stages
    __half* Bs = sm16 + 4 * CH16;              // 4 stages
    float* cs = (float*)(sm16 + 8 * CH16);
    float* cq = cs + 128;

    int tid = threadIdx.x;
    int wid = tid >> 5, lane = tid & 31;
    int g = lane >> 2, t = lane & 3;
    int warpM = wid >> 2, warpN = wid & 3;
    int m0 = blockIdx.x * 128;

    if (tid < 128) { cs[tid] = 0.f; cq[tid] = 0.f; }

    uint32_t sbA = smem_u32(As), sbB = smem_u32(Bs);

    int lane7 = lane & 7;
    int aRow = ((lane >> 3) & 1) * 8 + lane7;
    int aK   = ((lane >> 4) & 1) * 8;
    int bRow = ((lane >> 4) & 1) * 8 + lane7;
    int bK   = ((lane >> 3) & 1) * 8;

    auto issue = [&](int kk, int st) {
        uint32_t ab = sbA + (uint32_t)(st * CH16) * 2u;
#pragma unroll
        for (int i = 0; i < 2; i++) {
            int slot = tid + i * 256;
            int row = slot >> 2, seg = slot & 3;
            int gm = m0 + row;
            const __half* gp = (kk < 4)
                ? (g_h16 + (size_t)gm * DD + kk * 32 + seg * 8)
                : (g_neigh16 + (size_t)gm * DD + (kk - 4) * 32 + seg * 8);
            cp16(ab + row * (STRD16 * 2) + seg * 16, gp, gm < NN);
        }
        uint32_t bb = sbB + (uint32_t)(st * CH16) * 2u;
#pragma unroll
        for (int i = 0; i < 2; i++) {
            int slot = tid + i * 256;
            int row = slot >> 2, seg = slot & 3;
            cp16(bb + row * (STRD16 * 2) + seg * 16,
                 g_Wt16 + (size_t)row * 256 + kk * 32 + seg * 8, true);
        }
        CP_COMMIT();
    };

    float acc[4][4][4];
#pragma unroll
    for (int a = 0; a < 4; a++)
#pragma unroll
        for (int b = 0; b < 4; b++)
#pragma unroll
            for (int c = 0; c < 4; c++) acc[a][b][c] = 0.f;

    issue(0, 0);
    issue(1, 1);

#pragma unroll
    for (int kk = 0; kk < 8; kk++) {
        if (kk < 6) issue(kk + 2, (kk + 2) & 3);
        if (kk < 6)       { CP_WAIT(2); }
        else if (kk == 6) { CP_WAIT(1); }
        else              { CP_WAIT(0); }
        __syncthreads();

        int st = kk & 3;
        uint32_t ab = sbA + (uint32_t)(st * CH16) * 2u;
        uint32_t bb = sbB + (uint32_t)(st * CH16) * 2u;
#pragma unroll
        for (int ks = 0; ks < 2; ks++) {
            int kb = ks * 16;
            uint32_t bf[4][2];
#pragma unroll
            for (int pair = 0; pair < 2; pair++) {
                int nb = warpN * 32 + pair * 16;
                uint32_t addr = bb + (uint32_t)((nb + bRow) * STRD16 + kb + bK) * 2u;
                ldsm_x4(bf[2 * pair][0], bf[2 * pair][1],
                        bf[2 * pair + 1][0], bf[2 * pair + 1][1], addr);
            }
#pragma unroll
            for (int mf = 0; mf < 4; mf++) {
                int m = warpM * 64 + mf * 16;
                uint32_t a0, a1, a2, a3;
                uint32_t addr = ab + (uint32_t)((m + aRow) * STRD16 + kb + aK) * 2u;
                ldsm_x4(a0, a1, a2, a3, addr);
#pragma unroll
                for (int nf = 0; nf < 4; nf++)
                    mma16(acc[mf][nf], a0, a1, a2, a3, bf[nf][0], bf[nf][1]);
            }
        }
    }

    // ---- epilogue: bias + relu, fp16 store, per-block BN partials (fp32 exact) ----
#pragma unroll
    for (int nf = 0; nf < 4; nf++) {
        int col = warpN * 32 + nf * 8 + 2 * t;
        float2 bv = *(const float2*)(bias + col);
        float s0 = 0.f, s1 = 0.f, q0 = 0.f, q1 = 0.f;
#pragma unroll
        for (int mf = 0; mf < 4; mf++) {
#pragma unroll
            for (int hh = 0; hh < 2; hh++) {
                int row = m0 + warpM * 64 + mf * 16 + g + hh * 8;
                float v0 = fmaxf(acc[mf][nf][hh * 2 + 0] + bv.x, 0.f);
                float v1 = fmaxf(acc[mf][nf][hh * 2 + 1] + bv.y, 0.f);
                if (row < NN) {
                    __half2 p = __float22half2_rn(make_float2(v0, v1));
                    *(__half2*)(g_rst16 + (size_t)row * DD + col) = p;
                    s0 += v0; q0 += v0 * v0;
                    s1 += v1; q1 += v1 * v1;
                }
            }
        }
        atomicAdd(&cs[col], s0);     atomicAdd(&cs[col + 1], s1);
        atomicAdd(&cq[col], q0);     atomicAdd(&cq[col + 1], q1);
    }
    __syncthreads();
    if (tid < 128) {
        atomicAdd(&g_colsum[tid], cs[tid]);
        atomicAdd(&g_colsumsq[tid], cq[tid]);
    }
}

// ---------------------------------------------------------------- normalize + residual (BN fold inline)
__global__ __launch_bounds__(256) void k_final(const float* __restrict__ h,
                                               const float* __restrict__ gamma,
                                               const float* __restrict__ beta,
                                               float* __restrict__ out) {
    __shared__ float s_scale[DD];
    __shared__ float s_shift[DD];
    if (threadIdx.x < DD) {
        int j = threadIdx.x;
        float mean = g_colsum[j] / (float)NN;
        float var = g_colsumsq[j] / (float)NN - mean * mean;
        float rs = rsqrtf(var + BN_EPS);
        float sc = rs * gamma[j];
        s_scale[j] = sc;
        s_shift[j] = beta[j] - mean * sc;
    }
    __syncthreads();

    int i4 = blockIdx.x * blockDim.x + threadIdx.x;
    const int TOT = NN * DD / 4;
    if (i4 >= TOT) return;
    int c4 = i4 & 31;
    uint2 u = ((const uint2*)g_rst16)[i4];
    float2 r0 = __half22float2(*(__half2*)&u.x);
    float2 r1 = __half22float2(*(__half2*)&u.y);
    float4 hv = ((const float4*)h)[i4];
    float4 sc = *((const float4*)s_scale + c4);
    float4 sh = *((const float4*)s_shift + c4);
    float4 o;
    o.x = hv.x + r0.x * sc.x + sh.x;
    o.y = hv.y + r0.y * sc.y + sh.y;
    o.z = hv.z + r1.x * sc.z + sh.z;
    o.w = hv.w + r1.y * sc.w + sh.w;
    ((float4*)out)[i4] = o;
}

// ---------------------------------------------------------------- launch
extern "C" void kernel_launch(void* const* d_in, const int* in_sizes, int n_in,
                              void* d_out, int out_size) {
    const float* h     = (const float*)d_in[0];
    const int*   src   = (const int*)d_in[1];
    const int*   dst   = (const int*)d_in[2];
    const float* Ws    = (const float*)d_in[3];
    const float* Wn    = (const float*)d_in[4];
    const float* bias  = (const float*)d_in[5];
    const float* gamma = (const float*)d_in[6];
    const float* beta  = (const float*)d_in[7];
    float* out = (float*)d_out;

    const int GEMM_SMEM = 8 * CH16 * 2 + 256 * 4;   // 81920 + 1024
    static bool attr_set = false;
    if (!attr_set) {
        cudaFuncSetAttribute(k_gemm, cudaFuncAttributeMaxDynamicSharedMemorySize, GEMM_SMEM);
        attr_set = true;
    }

    k_zero<<<(NN + 255) / 256, 256>>>();
    k_build<<<FUSED_BLOCKS, 256>>>(dst, src, h, Ws, Wn);
    k_aggregate<<<(NN * 32 + 255) / 256, 256>>>();
    k_gemm<<<(NN + 127) / 128, 256, GEMM_SMEM>>>(bias);
    k_final<<<(NN * DD / 4 + 255) / 256, 256>>>(h, gamma, beta, out);
}